// round 17
// baseline (speedup 1.0000x reference)
#include <cuda_runtime.h>
#include <cuda_fp16.h>
#include <cstdint>

// ---------------------------------------------------------------------------
// Problem constants
// ---------------------------------------------------------------------------
static constexpr int B_  = 4;
static constexpr int C_  = 64;
static constexpr int H_  = 256;
static constexpr int W_  = 512;
static constexpr int HW  = H_ * W_;               // 131072 = 2^17
static constexpr int SW_ = 3 * W_;                // 1536
static constexpr int TILE_P = 512;                // one full image row
static constexpr int TILES_PER_B = HW / TILE_P;   // 256
static constexpr int N_TILES = B_ * TILES_PER_B;  // 1024
static constexpr int THREADS = 512;               // 16 warps, 32 px/warp

// W: per-thread B-fragment records: [tap][ks][lane] 64B, chunk-XOR swizzled
static constexpr int W_TAP_B   = 4 * 2048;                  // 8192
static constexpr int W_BYTES   = 9 * W_TAP_B;               // 73728

static constexpr int SMEM_W    = 0;
static constexpr int SMEM_BIAS = W_BYTES;                   // 256 B
static constexpr int SMEM_TOTAL = W_BYTES + 256;            // 73984

__device__ int g_idx_is64;
// xt rows are 128B, intra-row FRAGMENT-PERMUTED:
//   half2 index c2 (0..31) -> byte (c2&3)*32 + (c2>>3)*8 + ((c2>>2)&1)*4
// A thread (tig) reads its whole-tap fragment share of one row as one
// contiguous 32B block at offset tig*32 (2 x LDG.128).
__device__ __align__(128) __half g_xt[(size_t)B_ * HW * C_];

// ---------------------------------------------------------------------------
// PTX helpers
// ---------------------------------------------------------------------------
__device__ __forceinline__ uint32_t smem_u32(const void* p) {
    uint32_t a;
    asm("{ .reg .u64 t; cvta.to.shared.u64 t, %1; cvt.u32.u64 %0, t; }" : "=r"(a) : "l"(p));
    return a;
}

__device__ __forceinline__ void lds128(uint32_t* q, uint32_t addr) {
    asm volatile("ld.shared.v4.b32 {%0,%1,%2,%3}, [%4];"
                 : "=r"(q[0]), "=r"(q[1]), "=r"(q[2]), "=r"(q[3]) : "r"(addr));
}

__device__ __forceinline__ void mma_f16(float* c, uint32_t a0, uint32_t a1,
                                        uint32_t a2, uint32_t a3,
                                        uint32_t b0, uint32_t b1) {
    asm volatile(
        "mma.sync.aligned.m16n8k16.row.col.f32.f16.f16.f32 "
        "{%0,%1,%2,%3}, {%4,%5,%6,%7}, {%8,%9}, {%0,%1,%2,%3};"
        : "+f"(c[0]), "+f"(c[1]), "+f"(c[2]), "+f"(c[3])
        : "r"(a0), "r"(a1), "r"(a2), "r"(a3), "r"(b0), "r"(b1));
}

// ---------------------------------------------------------------------------
// Kernel 1: transpose x [B][C][HW] -> g_xt [B][HW][C] fp16 with the fragment
//   permutation.  Tile: 64 channels x 32 hw, 256 threads.  Stores are one
//   16B uint4 per thread, warps covering 4 consecutive 128B rows (coalesced).
//   Block (0,0,0) also detects idx dtype.
// ---------------------------------------------------------------------------
__global__ void transpose_kernel(const float* __restrict__ x,
                                 const unsigned int* __restrict__ idxw) {
    if (blockIdx.x == 0 && blockIdx.z == 0 &&
        threadIdx.x == 0 && threadIdx.y == 0) {
        int is64 = 1;
        for (int i = 0; i < 64; ++i)
            if (idxw[2 * i + 1] != 0u) { is64 = 0; break; }
        g_idx_is64 = is64;
    }
    __shared__ float t[64][33];
    const int b  = blockIdx.z;
    const int gb = blockIdx.x * 32;
    const int tx = threadIdx.x, ty = threadIdx.y;   // (32, 8)
    const float* xb = x + (size_t)b * C_ * HW;
#pragma unroll
    for (int i = 0; i < 64; i += 8)
        t[ty + i][tx] = xb[(size_t)(ty + i) * HW + gb + tx];
    __syncthreads();

    // store: thread q of each row writes bytes [16q, 16q+16)
    const int tid = ty * 32 + tx;       // 0..255
    const int hwl = tid >> 3;           // 0..31 row
    const int q   = tid & 7;            // 0..7 chunk
    const int a   = q >> 1;             // c2&3
    // chunk q covers c2 = a + 4b + 8d with 2d+b in [4(q&1), 4(q&1)+4)
    uint32_t u[4];
#pragma unroll
    for (int e = 0; e < 4; ++e) {
        int db = 4 * (q & 1) + e;       // 2d + b
        int d  = db >> 1, bb = db & 1;
        int c2 = a + 4 * bb + 8 * d;
        __half2 v = __floats2half2_rn(t[2 * c2][hwl], t[2 * c2 + 1][hwl]);
        u[(4 * bb + 8 * d) >> 2 & 3] = *(uint32_t*)&v;   // offset within 16B
    }
    char* dst = (char*)g_xt + (((size_t)b * HW + gb + hwl) << 7) + q * 16;
    *(uint4*)dst = make_uint4(u[0], u[1], u[2], u[3]);
}

// ---------------------------------------------------------------------------
// Kernel 2: persistent fused kernel, NO smem A, NO barriers in the loop.
//   Direct-LDG A fragments from permuted g_xt, B fragments from smem W,
//   bias folded into acc init, incremental tap offset (no division).
// ---------------------------------------------------------------------------
struct Cur {
    int tile; int tap; int off;   // off = kh*1536 + kw
    __device__ __forceinline__ void adv(int stride) {
        ++tap;
        if (tap == 9) { tap = 0; off = 0; tile += stride; }
        else if (tap == 3 || tap == 6) off += SW_ - 2;   // kh+1, kw-2
        else ++off;
    }
};

__global__ void __launch_bounds__(THREADS, 1)
latconv_main(const void* __restrict__ idx_raw,
             const float* __restrict__ wgt,
             const float* __restrict__ bias,
             float* __restrict__ out) {
    extern __shared__ char smem[];
    const uint32_t wbase = smem_u32(smem + SMEM_W);
    float* bsm = (float*)(smem + SMEM_BIAS);

    const int tid = threadIdx.x;
    const int wid = tid >> 5;       // 0..15
    const int lid = tid & 31;
    const int gid = lid >> 2;       // 0..7
    const int tig = lid & 3;        // 0..3
    const int is64 = g_idx_is64;
    const uint32_t bsw = (uint32_t)((lid >> 1) & 3);   // B chunk swizzle

    // Stage weights fp16 as per-thread B-fragment records.
    for (int e = tid; e < C_ * C_ * 9; e += THREADS) {
        int ci = e & 63, co = (e >> 6) & 63, j = e >> 12;
        int nt = co >> 3, gw = co & 7;
        int ks = ci >> 4, r = ci & 15;
        int bsel = r >> 3, tw = (r & 7) >> 1, lo = r & 1;
        int lane = gw * 4 + tw;
        int c = nt >> 1, u = ((nt & 1) << 1) + bsel;
        uint32_t off = (uint32_t)(j * W_TAP_B + ks * 2048 + lane * 64
                     + ((c ^ ((lane >> 1) & 3)) << 4) + (u << 2) + (lo << 1));
        *(__half*)(smem + SMEM_W + off) = __float2half_rn(wgt[co * 576 + ci * 9 + j]);
    }
    if (tid < C_) bsm[tid] = bias[tid];
    __syncthreads();

    // my 4 fragment rows within the tile: wid*32 + gid + rs*8
    const int myrow  = wid * 32 + gid;
    const int myrow3 = 3 * myrow;

    // idx prefetch cursor
    Cur c_nxt = {(int)blockIdx.x, 0, 0};
    int gi[4];
    {
        int pt = c_nxt.tile & (TILES_PER_B - 1);
        int ob = pt * (3 * SW_) + myrow3;       // tap 0
#pragma unroll
        for (int rs = 0; rs < 4; ++rs) {
            int o = ob + 24 * rs;
            gi[rs] = is64 ? (int)__ldg((const long long*)idx_raw + o)
                          : __ldg((const int*)idx_raw + o);
        }
    }
    c_nxt.adv(gridDim.x);

    float acc[2][8][4];

    for (int tile = blockIdx.x; tile < N_TILES; tile += gridDim.x) {
        const char* base = (const char*)g_xt + ((size_t)(tile >> 8) << 24);

#pragma unroll 1
        for (int j = 0; j < 9; ++j) {
            // ---- issue A fragment loads for this tap (uses gi) ----
            uint32_t ar[4][8];
#pragma unroll
            for (int rs = 0; rs < 4; ++rs) {
                const char* rb = base + ((uint32_t)gi[rs] << 7) + tig * 32;
                uint4 v0 = __ldg((const uint4*)rb);
                uint4 v1 = __ldg((const uint4*)(rb + 16));
                ar[rs][0] = v0.x; ar[rs][1] = v0.y;
                ar[rs][2] = v0.z; ar[rs][3] = v0.w;
                ar[rs][4] = v1.x; ar[rs][5] = v1.y;
                ar[rs][6] = v1.z; ar[rs][7] = v1.w;
            }

            // ---- prefetch idx for the next step ----
            if (c_nxt.tile < N_TILES) {
                int pt = c_nxt.tile & (TILES_PER_B - 1);
                int ob = pt * (3 * SW_) + c_nxt.off + myrow3;
#pragma unroll
                for (int rs = 0; rs < 4; ++rs) {
                    int o = ob + 24 * rs;
                    gi[rs] = is64 ? (int)__ldg((const long long*)idx_raw + o)
                                  : __ldg((const int*)idx_raw + o);
                }
            }
            c_nxt.adv(gridDim.x);

            if (j == 0) {
                // init acc with bias (folds epilogue adds)
#pragma unroll
                for (int nt = 0; nt < 8; ++nt) {
                    float2 bb = *(const float2*)(bsm + nt * 8 + 2 * tig);
#pragma unroll
                    for (int mh = 0; mh < 2; ++mh) {
                        acc[mh][nt][0] = bb.x; acc[mh][nt][1] = bb.y;
                        acc[mh][nt][2] = bb.x; acc[mh][nt][3] = bb.y;
                    }
                }
            }

            // ---- compute: 4 ks x (4 B-lds128 + 16 mma) ----
            const uint32_t wtap = wbase + (uint32_t)j * W_TAP_B
                                + (uint32_t)lid * 64;
#pragma unroll
            for (int ks = 0; ks < 4; ++ks) {
                const uint32_t wks = wtap + (uint32_t)ks * 2048;
#pragma unroll
                for (int c = 0; c < 4; ++c) {
                    uint32_t q[4];
                    lds128(q, wks + ((c ^ bsw) << 4));
                    mma_f16(acc[0][2 * c],
                            ar[0][2 * ks], ar[1][2 * ks],
                            ar[0][2 * ks + 1], ar[1][2 * ks + 1], q[0], q[1]);
                    mma_f16(acc[1][2 * c],
                            ar[2][2 * ks], ar[3][2 * ks],
                            ar[2][2 * ks + 1], ar[3][2 * ks + 1], q[0], q[1]);
                    mma_f16(acc[0][2 * c + 1],
                            ar[0][2 * ks], ar[1][2 * ks],
                            ar[0][2 * ks + 1], ar[1][2 * ks + 1], q[2], q[3]);
                    mma_f16(acc[1][2 * c + 1],
                            ar[2][2 * ks], ar[3][2 * ks],
                            ar[2][2 * ks + 1], ar[3][2 * ks + 1], q[2], q[3]);
                }
            }
        }

        // ---- epilogue: direct STG (bias already in acc) ----
        {
            int b  = tile >> 8;
            int pt = tile & (TILES_PER_B - 1);
            float* op = out + ((size_t)b << 23) + (size_t)pt * TILE_P;
#pragma unroll
            for (int mh = 0; mh < 2; ++mh) {
                int px = wid * 32 + mh * 16 + gid;
#pragma unroll
                for (int nt = 0; nt < 8; ++nt) {
                    int co = nt * 8 + 2 * tig;
                    float* q = op + (size_t)co * HW + px;
                    q[0]      = acc[mh][nt][0];
                    q[HW]     = acc[mh][nt][1];
                    q[8]      = acc[mh][nt][2];
                    q[HW + 8] = acc[mh][nt][3];
                }
            }
        }
    }
}

// ---------------------------------------------------------------------------
// Launch
// ---------------------------------------------------------------------------
extern "C" void kernel_launch(void* const* d_in, const int* in_sizes, int n_in,
                              void* d_out, int out_size) {
    const float* x    = (const float*)d_in[0];
    const void*  idx  = d_in[1];
    const float* wgt  = (const float*)d_in[2];
    const float* bias = (const float*)d_in[3];
    float* out        = (float*)d_out;

    dim3 tb(32, 8);
    dim3 tg(HW / 32, 1, B_);
    transpose_kernel<<<tg, tb>>>(x, (const unsigned int*)idx);

    cudaFuncSetAttribute(latconv_main, cudaFuncAttributeMaxDynamicSharedMemorySize,
                         SMEM_TOTAL);
    int sm_count = 0;
    cudaDeviceGetAttribute(&sm_count, cudaDevAttrMultiProcessorCount, 0);
    if (sm_count <= 0) sm_count = 148;

    latconv_main<<<sm_count, THREADS, SMEM_TOTAL>>>(idx, wgt, bias, out);
}